// round 14
// baseline (speedup 1.0000x reference)
#include <cuda_runtime.h>
#include <cuda_fp16.h>
#include <cstdint>
#include <math.h>

// Problem constants
#define N_    1024
#define L_    128
#define WD_   300
#define PD_   50
#define D_    400          // WD + 2*PD
#define FS_   3
#define NF_   512
#define C_    53
#define LP_   126          // L - FS + 1
#define KTOT  1200         // FS * D
#define KPAD  1216         // padded to 19*64
#define KC    64
#define NKC   19
#define NEG_  (-1e30f)
#define F3    (3 * NF_)

// ---------------------------------------------------------------------------
// Scratch (device globals; no allocs allowed)
// ---------------------------------------------------------------------------
__device__ __align__(256) __half g_X[(size_t)N_ * L_ * D_ + 2048];   // fp16 X
__device__ __align__(256) __half g_W[NF_ * KPAD];                    // fp16 W
__device__ float g_feat[(size_t)N_ * F3];        // [n][f*3+seg]

// ---------------------------------------------------------------------------
// Helpers (baseline ISA only: cp.async / ldmatrix / mma.sync)
// ---------------------------------------------------------------------------
__device__ __forceinline__ uint32_t smem_u32(const void* p) {
    uint32_t a;
    asm("{ .reg .u64 t; cvta.to.shared.u64 t, %1; cvt.u32.u64 %0, t; }" : "=r"(a) : "l"(p));
    return a;
}
#define CP_ASYNC16(dst, src) \
    asm volatile("cp.async.cg.shared.global [%0], [%1], 16;" :: "r"(dst), "l"(src) : "memory")
#define CP_COMMIT()  asm volatile("cp.async.commit_group;" ::: "memory")
#define CP_WAIT1()   asm volatile("cp.async.wait_group 1;" ::: "memory")
#define CP_WAIT0()   asm volatile("cp.async.wait_group 0;" ::: "memory")

#define LDSM_X4(d0, d1, d2, d3, addr) \
    asm volatile("ldmatrix.sync.aligned.m8n8.x4.shared.b16 {%0,%1,%2,%3}, [%4];" \
                 : "=r"(d0), "=r"(d1), "=r"(d2), "=r"(d3) : "r"(addr))

#define MMAF16(cc, a0, a1, a2, a3, b0, b1) \
    asm volatile("mma.sync.aligned.m16n8k16.row.col.f32.f16.f16.f32 " \
                 "{%0,%1,%2,%3}, {%4,%5,%6,%7}, {%8,%9}, {%0,%1,%2,%3};" \
                 : "+f"((cc)[0]), "+f"((cc)[1]), "+f"((cc)[2]), "+f"((cc)[3]) \
                 : "r"(a0), "r"(a1), "r"(a2), "r"(a3), "r"(b0), "r"(b1))

// ---------------------------------------------------------------------------
// Kernel 1: embedding gather -> fp16 (R11-proven version)
// ---------------------------------------------------------------------------
__global__ __launch_bounds__(128) void gather_kernel(
    const int* __restrict__ tokens, const int* __restrict__ pf1,
    const int* __restrict__ pf2,
    const float* __restrict__ wordvec, const float* __restrict__ pf1_emb,
    const float* __restrict__ pf2_emb)
{
    int id = blockIdx.x;                     // (n,l)
    size_t base = (size_t)id * D_;
    int t = threadIdx.x;
    if (t < 75) {
        float4 v = reinterpret_cast<const float4*>(wordvec + (size_t)tokens[id] * WD_)[t];
        __half h[4] = {__float2half(v.x), __float2half(v.y),
                       __float2half(v.z), __float2half(v.w)};
        *reinterpret_cast<uint2*>(&g_X[base + t * 4]) = *reinterpret_cast<uint2*>(h);
    } else if (t < 100) {
        int j = t - 75;
        float2 v = reinterpret_cast<const float2*>(pf1_emb + pf1[id] * PD_)[j];
        __half h[2] = {__float2half(v.x), __float2half(v.y)};
        *reinterpret_cast<uint32_t*>(&g_X[base + WD_ + j * 2]) = *reinterpret_cast<uint32_t*>(h);
    } else if (t < 125) {
        int j = t - 100;
        float2 v = reinterpret_cast<const float2*>(pf2_emb + pf2[id] * PD_)[j];
        __half h[2] = {__float2half(v.x), __float2half(v.y)};
        *reinterpret_cast<uint32_t*>(&g_X[base + WD_ + PD_ + j * 2]) = *reinterpret_cast<uint32_t*>(h);
    }
}

// ---------------------------------------------------------------------------
// Kernel 1b: convert conv_w to fp16, zero-padded K 1200->1216
// ---------------------------------------------------------------------------
__global__ __launch_bounds__(256) void wconv_kernel(const float* __restrict__ conv_w)
{
    int idx = blockIdx.x * 256 + threadIdx.x;      // 0 .. NF_*KPAD-1
    int f = idx / KPAD, k = idx % KPAD;
    float v = (k < KTOT) ? conv_w[(size_t)f * KTOT + k] : 0.f;
    g_W[idx] = __float2half(v);
}

// ---------------------------------------------------------------------------
// Kernel 2: fp16 mma.sync conv GEMM + tanh + pool.
// Grid (2, N_): blockIdx.x = filter half (256 f), blockIdx.y = sentence.
// 8 warps = 2(M) x 4(N); warp tile 64x64; CTA tile 128x256; 1 CTA/SM.
// LDSM traffic: 8 LDSM/warp/ks -> 128KB/SM/kc (vs 192KB at R11's 32x64
// with 2 CTAs) -- crossbar model predicts conv x0.67.
// R11's PROVEN 2-stage pipeline + inner-loop shape; no frag double-buffer.
// ---------------------------------------------------------------------------
#define STAGE_SZ 49152
#define B_OFF    16384
#define SM_BIAS  135168       // after epilogue red region (128*264*4)
#define SM_DYN   136192
#define RED_STR  264          // 256 cols + 8 pad

struct LoadCtx { size_t xbase; int nb; };

__device__ __forceinline__ void load_stage(uint32_t sbase, int tid,
                                           const LoadCtx& lc, int k0)
{
#pragma unroll
    for (int i = 0; i < 4; i++) {          // A: 128 rows x 8 chunks of 16B
        int idx = tid + i * 256;
        int r = idx >> 3, c = idx & 7;
        uint32_t d = sbase + r * 128 + ((uint32_t)(c ^ (r & 7)) << 4);
        CP_ASYNC16(d, g_X + lc.xbase + (size_t)r * D_ + k0 + c * 8);
    }
#pragma unroll
    for (int i = 0; i < 8; i++) {          // B: 256 rows x 8 chunks of 16B
        int idx = tid + i * 256;
        int r = idx >> 3, c = idx & 7;
        uint32_t d = sbase + B_OFF + r * 128 + ((uint32_t)(c ^ (r & 7)) << 4);
        CP_ASYNC16(d, g_W + (size_t)(lc.nb * 256 + r) * KPAD + k0 + c * 8);
    }
}

__global__ __launch_bounds__(256, 1) void conv_hmma_kernel(
    const float* __restrict__ conv_b, const int* __restrict__ entity_pos)
{
    extern __shared__ char smem[];
    const uint32_t sb = smem_u32(smem);
    const int tid  = threadIdx.x;
    const int lane = tid & 31, wid = tid >> 5;
    const int wm = wid & 1, wn = wid >> 1;       // warp grid 2(M) x 4(N)
    const int nb = blockIdx.x;                    // filter half (256 f)
    const int n  = blockIdx.y;                    // sentence

    float* biasS = reinterpret_cast<float*>(smem + SM_BIAS);
    biasS[tid] = conv_b[nb * 256 + tid];

    LoadCtx lc;
    lc.xbase = (size_t)n * (L_ * D_);
    lc.nb = nb;

    // ldmatrix lane addressing (verified fragment maps; A rows wm*64+i*16,
    // B rows wn*64+j*16)
    const int rowA = wm * 64 + ((lane >> 3) & 1) * 8 + (lane & 7);
    const int haA  = lane >> 4;
    const uint32_t offA = rowA * 128;
    const int saA = rowA & 7;
    const int rowB = wn * 64 + ((lane >> 4) & 1) * 8 + (lane & 7);
    const int hbB  = (lane >> 3) & 1;
    const uint32_t offB = rowB * 128;
    const int sbB = rowB & 7;

    float acc[4][8][4];                           // [m16 i][n8 q][4] = 128 regs
#pragma unroll
    for (int i = 0; i < 4; i++)
#pragma unroll
        for (int q = 0; q < 8; q++)
#pragma unroll
            for (int v = 0; v < 4; v++) acc[i][q][v] = 0.f;

    load_stage(sb, tid, lc, 0);
    CP_COMMIT();

    for (int kc = 0; kc < NKC; kc++) {
        if (kc + 1 < NKC) {
            load_stage(sb + ((kc + 1) & 1) * STAGE_SZ, tid, lc, (kc + 1) * KC);
            CP_COMMIT();
            CP_WAIT1();
        } else {
            CP_WAIT0();
        }
        __syncthreads();

        const uint32_t stg = sb + (kc & 1) * STAGE_SZ;
#pragma unroll
        for (int ks = 0; ks < 4; ks++) {
            uint32_t a[4][4];
#pragma unroll
            for (int i = 0; i < 4; i++) {
                uint32_t ad = stg + offA + i * 2048
                            + ((uint32_t)((ks * 2 + haA) ^ saA) << 4);
                LDSM_X4(a[i][0], a[i][1], a[i][2], a[i][3], ad);
            }
#pragma unroll
            for (int j = 0; j < 4; j++) {
                uint32_t b0, b1, b2, b3;
                uint32_t bd = stg + B_OFF + offB + j * 2048
                            + ((uint32_t)((ks * 2 + hbB) ^ sbB) << 4);
                LDSM_X4(b0, b1, b2, b3, bd);
#pragma unroll
                for (int i = 0; i < 4; i++) {
                    MMAF16(acc[i][j * 2],     a[i][0], a[i][1], a[i][2], a[i][3], b0, b1);
                    MMAF16(acc[i][j * 2 + 1], a[i][0], a[i][1], a[i][2], a[i][3], b2, b3);
                }
            }
        }
        __syncthreads();
    }

    // ---- epilogue: bias + tanh -> smem, then 3-segment max over t ----
    float* red = reinterpret_cast<float*>(smem);        // [128][RED_STR]
    const int r0b = wm * 64 + (lane >> 2);
    const int c0b = wn * 64 + (lane & 3) * 2;
#pragma unroll
    for (int i = 0; i < 4; i++) {
#pragma unroll
        for (int q = 0; q < 8; q++) {
            const int r0 = r0b + i * 16;
            const int c0 = c0b + q * 8;
            red[r0 * RED_STR + c0]           = tanhf(acc[i][q][0] + biasS[c0]);
            red[r0 * RED_STR + c0 + 1]       = tanhf(acc[i][q][1] + biasS[c0 + 1]);
            red[(r0 + 8) * RED_STR + c0]     = tanhf(acc[i][q][2] + biasS[c0]);
            red[(r0 + 8) * RED_STR + c0 + 1] = tanhf(acc[i][q][3] + biasS[c0 + 1]);
        }
    }
    __syncthreads();

    const int p1 = entity_pos[2 * n];
    const int p2 = entity_pos[2 * n + 1];
    {
        const int c = tid;                               // column 0..255
        float m0 = NEG_, m1 = NEG_, m2 = NEG_;
        for (int t = 0; t < LP_; t++) {
            float v = red[t * RED_STR + c];
            if (t <= p1) m0 = fmaxf(m0, v);
            if (t >= p1 && t <= p2) m1 = fmaxf(m1, v);
            if (t >= p2) m2 = fmaxf(m2, v);
        }
        const size_t fo = (size_t)n * F3 + (size_t)(nb * 256 + c) * 3;
        g_feat[fo + 0] = m0;
        g_feat[fo + 1] = m1;
        g_feat[fo + 2] = m2;
    }
}

// ---------------------------------------------------------------------------
// Kernel 3: out[n][c] = feat[n] @ out_w + out_b  (R11-proven version)
// ---------------------------------------------------------------------------
__global__ __launch_bounds__(256) void out_gemm_kernel(
    const float* __restrict__ out_w, const float* __restrict__ out_b,
    float* __restrict__ out)
{
    __shared__ float sf[F3];
    __shared__ float part[4][64];
    const int n = blockIdx.x;

    for (int i = threadIdx.x; i < F3; i += 256)
        sf[i] = g_feat[(size_t)n * F3 + i];
    __syncthreads();

    const int g = threadIdx.x >> 6;
    const int c = threadIdx.x & 63;
    float a = 0.f;
    if (c < C_) {
        const int j0 = g * (F3 / 4);
#pragma unroll 4
        for (int j = j0; j < j0 + (F3 / 4); j++)
            a += sf[j] * out_w[j * C_ + c];
    }
    part[g][c] = a;
    __syncthreads();

    if (threadIdx.x < C_) {
        float s = part[0][threadIdx.x] + part[1][threadIdx.x] +
                  part[2][threadIdx.x] + part[3][threadIdx.x] + out_b[threadIdx.x];
        out[(size_t)n * C_ + threadIdx.x] = s;
    }
}

// ---------------------------------------------------------------------------
// Launch. Inputs: tokens, pf1, pf2, entity_pos, wordvec, pf1_emb, pf2_emb,
// conv_w, conv_b, out_w, out_b.  Output: float32 [N, C].
// ---------------------------------------------------------------------------
extern "C" void kernel_launch(void* const* d_in, const int* in_sizes, int n_in,
                              void* d_out, int out_size)
{
    const int*   tokens     = (const int*)d_in[0];
    const int*   pf1        = (const int*)d_in[1];
    const int*   pf2        = (const int*)d_in[2];
    const int*   entity_pos = (const int*)d_in[3];
    const float* wordvec    = (const float*)d_in[4];
    const float* pf1_emb    = (const float*)d_in[5];
    const float* pf2_emb    = (const float*)d_in[6];
    const float* conv_w     = (const float*)d_in[7];
    const float* conv_b     = (const float*)d_in[8];
    const float* out_w      = (const float*)d_in[9];
    const float* out_b      = (const float*)d_in[10];
    float* out = (float*)d_out;

    cudaFuncSetAttribute(conv_hmma_kernel,
                         cudaFuncAttributeMaxDynamicSharedMemorySize, SM_DYN);

    gather_kernel<<<N_ * L_, 128>>>(tokens, pf1, pf2, wordvec, pf1_emb, pf2_emb);
    wconv_kernel<<<(NF_ * KPAD) / 256, 256>>>(conv_w);
    conv_hmma_kernel<<<dim3(2, N_), 256, SM_DYN>>>(conv_b, entity_pos);
    out_gemm_kernel<<<N_, 256>>>(out_w, out_b, out);
}

// round 16
// speedup vs baseline: 1.0881x; 1.0881x over previous
#include <cuda_runtime.h>
#include <cuda_fp16.h>
#include <cstdint>
#include <math.h>

// Problem constants
#define N_    1024
#define L_    128
#define WD_   300
#define PD_   50
#define D_    400          // WD + 2*PD
#define FS_   3
#define NF_   512
#define C_    53
#define LP_   126          // L - FS + 1
#define KTOT  1200         // FS * D
#define KPAD  1216         // padded to 19*64
#define KC    64
#define NKC   19
#define NEG_  (-1e30f)
#define F3    (3 * NF_)

// ---------------------------------------------------------------------------
// Scratch (device globals; no allocs allowed)
// ---------------------------------------------------------------------------
__device__ __align__(256) __half g_X[(size_t)N_ * L_ * D_ + 2048];   // fp16 X
__device__ __align__(256) __half g_W[NF_ * KPAD];                    // fp16 W
__device__ float g_feat[(size_t)N_ * F3];        // [n][f*3+seg]

// ---------------------------------------------------------------------------
// Helpers (baseline ISA only: cp.async / ldmatrix / mma.sync)
// ---------------------------------------------------------------------------
__device__ __forceinline__ uint32_t smem_u32(const void* p) {
    uint32_t a;
    asm("{ .reg .u64 t; cvta.to.shared.u64 t, %1; cvt.u32.u64 %0, t; }" : "=r"(a) : "l"(p));
    return a;
}
#define CP_ASYNC16(dst, src) \
    asm volatile("cp.async.cg.shared.global [%0], [%1], 16;" :: "r"(dst), "l"(src) : "memory")
#define CP_COMMIT()  asm volatile("cp.async.commit_group;" ::: "memory")
#define CP_WAIT1()   asm volatile("cp.async.wait_group 1;" ::: "memory")
#define CP_WAIT0()   asm volatile("cp.async.wait_group 0;" ::: "memory")

#define LDSM_X4(d0, d1, d2, d3, addr) \
    asm volatile("ldmatrix.sync.aligned.m8n8.x4.shared.b16 {%0,%1,%2,%3}, [%4];" \
                 : "=r"(d0), "=r"(d1), "=r"(d2), "=r"(d3) : "r"(addr))

#define MMAF16(cc, a0, a1, a2, a3, b0, b1) \
    asm volatile("mma.sync.aligned.m16n8k16.row.col.f32.f16.f16.f32 " \
                 "{%0,%1,%2,%3}, {%4,%5,%6,%7}, {%8,%9}, {%0,%1,%2,%3};" \
                 : "+f"((cc)[0]), "+f"((cc)[1]), "+f"((cc)[2]), "+f"((cc)[3]) \
                 : "r"(a0), "r"(a1), "r"(a2), "r"(a3), "r"(b0), "r"(b1))

// ---------------------------------------------------------------------------
// Kernel 1: embedding gather -> fp16 (R11-proven version, untouched)
// ---------------------------------------------------------------------------
__global__ __launch_bounds__(128) void gather_kernel(
    const int* __restrict__ tokens, const int* __restrict__ pf1,
    const int* __restrict__ pf2,
    const float* __restrict__ wordvec, const float* __restrict__ pf1_emb,
    const float* __restrict__ pf2_emb)
{
    int id = blockIdx.x;                     // (n,l)
    size_t base = (size_t)id * D_;
    int t = threadIdx.x;
    if (t < 75) {
        float4 v = reinterpret_cast<const float4*>(wordvec + (size_t)tokens[id] * WD_)[t];
        __half h[4] = {__float2half(v.x), __float2half(v.y),
                       __float2half(v.z), __float2half(v.w)};
        *reinterpret_cast<uint2*>(&g_X[base + t * 4]) = *reinterpret_cast<uint2*>(h);
    } else if (t < 100) {
        int j = t - 75;
        float2 v = reinterpret_cast<const float2*>(pf1_emb + pf1[id] * PD_)[j];
        __half h[2] = {__float2half(v.x), __float2half(v.y)};
        *reinterpret_cast<uint32_t*>(&g_X[base + WD_ + j * 2]) = *reinterpret_cast<uint32_t*>(h);
    } else if (t < 125) {
        int j = t - 100;
        float2 v = reinterpret_cast<const float2*>(pf2_emb + pf2[id] * PD_)[j];
        __half h[2] = {__float2half(v.x), __float2half(v.y)};
        *reinterpret_cast<uint32_t*>(&g_X[base + WD_ + PD_ + j * 2]) = *reinterpret_cast<uint32_t*>(h);
    }
}

// ---------------------------------------------------------------------------
// Kernel 1b: convert conv_w to fp16, zero-padded K 1200->1216
// ---------------------------------------------------------------------------
__global__ __launch_bounds__(256) void wconv_kernel(const float* __restrict__ conv_w)
{
    int idx = blockIdx.x * 256 + threadIdx.x;      // 0 .. NF_*KPAD-1
    int f = idx / KPAD, k = idx % KPAD;
    float v = (k < KTOT) ? conv_w[(size_t)f * KTOT + k] : 0.f;
    g_W[idx] = __float2half(v);
}

// ---------------------------------------------------------------------------
// Kernel 2: fp16 mma.sync conv GEMM + tanh + pool.  R11 config (proven 563):
// grid (4, N_), 8 warps = 4(M) x 2(N), warp tile 32x64, 2 CTAs/SM.
// ONE change vs R11: per ks, issue all 6 LDSM back-to-back (MLP hides LDS
// latency), then run the 16 MMAs dependency-free.
// ---------------------------------------------------------------------------
#define STAGE_SZ 32768
#define B_OFF    16384
#define SM_BIAS  70656
#define SM_DYN   71168
#define RED_STR  132

struct LoadCtx { size_t xbase; int nb; };

__device__ __forceinline__ void load_stage(uint32_t sbase, int tid,
                                           const LoadCtx& lc, int k0)
{
#pragma unroll
    for (int i = 0; i < 4; i++) {          // A: 128 rows x 8 chunks of 16B
        int idx = tid + i * 256;
        int r = idx >> 3, c = idx & 7;
        uint32_t d = sbase + r * 128 + ((uint32_t)(c ^ (r & 7)) << 4);
        CP_ASYNC16(d, g_X + lc.xbase + (size_t)r * D_ + k0 + c * 8);
    }
#pragma unroll
    for (int i = 0; i < 4; i++) {          // B: 128 rows x 8 chunks of 16B
        int idx = tid + i * 256;
        int r = idx >> 3, c = idx & 7;
        uint32_t d = sbase + B_OFF + r * 128 + ((uint32_t)(c ^ (r & 7)) << 4);
        CP_ASYNC16(d, g_W + (size_t)(lc.nb * 128 + r) * KPAD + k0 + c * 8);
    }
}

__global__ __launch_bounds__(256, 2) void conv_hmma_kernel(
    const float* __restrict__ conv_b, const int* __restrict__ entity_pos)
{
    extern __shared__ char smem[];
    const uint32_t sb = smem_u32(smem);
    const int tid  = threadIdx.x;
    const int lane = tid & 31, wid = tid >> 5;
    const int wm = wid & 3, wn = wid >> 2;       // warp grid 4(M) x 2(N)
    const int nb = blockIdx.x;                    // filter quarter
    const int n  = blockIdx.y;                    // sentence

    float* biasS = reinterpret_cast<float*>(smem + SM_BIAS);
    if (tid < 128) biasS[tid] = conv_b[nb * 128 + tid];

    LoadCtx lc;
    lc.xbase = (size_t)n * (L_ * D_);
    lc.nb = nb;

    const int rowA = wm * 32 + ((lane >> 3) & 1) * 8 + (lane & 7);
    const int haA  = lane >> 4;
    const uint32_t offA = rowA * 128;
    const int saA = rowA & 7;
    const int rowB = wn * 64 + ((lane >> 4) & 1) * 8 + (lane & 7);
    const int hbB  = (lane >> 3) & 1;
    const uint32_t offB = rowB * 128;
    const int sbB = rowB & 7;

    float acc[2][8][4];
#pragma unroll
    for (int i = 0; i < 2; i++)
#pragma unroll
        for (int q = 0; q < 8; q++)
#pragma unroll
            for (int v = 0; v < 4; v++) acc[i][q][v] = 0.f;

    load_stage(sb, tid, lc, 0);
    CP_COMMIT();

    for (int kc = 0; kc < NKC; kc++) {
        if (kc + 1 < NKC) {
            load_stage(sb + ((kc + 1) & 1) * STAGE_SZ, tid, lc, (kc + 1) * KC);
            CP_COMMIT();
            CP_WAIT1();
        } else {
            CP_WAIT0();
        }
        __syncthreads();

        const uint32_t stg = sb + (kc & 1) * STAGE_SZ;
#pragma unroll
        for (int ks = 0; ks < 4; ks++) {
            uint32_t a[2][4], b[4][4];
            // batch all 6 LDSM first: latencies overlap via MLP
#pragma unroll
            for (int i = 0; i < 2; i++) {
                uint32_t ad = stg + offA + i * 2048
                            + ((uint32_t)((ks * 2 + haA) ^ saA) << 4);
                LDSM_X4(a[i][0], a[i][1], a[i][2], a[i][3], ad);
            }
#pragma unroll
            for (int j = 0; j < 4; j++) {
                uint32_t bd = stg + B_OFF + offB + j * 2048
                            + ((uint32_t)((ks * 2 + hbB) ^ sbB) << 4);
                LDSM_X4(b[j][0], b[j][1], b[j][2], b[j][3], bd);
            }
            // then 16 MMAs with no outstanding smem dependency
#pragma unroll
            for (int j = 0; j < 4; j++) {
#pragma unroll
                for (int i = 0; i < 2; i++) {
                    MMAF16(acc[i][j * 2],     a[i][0], a[i][1], a[i][2], a[i][3],
                           b[j][0], b[j][1]);
                    MMAF16(acc[i][j * 2 + 1], a[i][0], a[i][1], a[i][2], a[i][3],
                           b[j][2], b[j][3]);
                }
            }
        }
        __syncthreads();
    }

    // ---- epilogue: bias + tanh -> smem, then 3-segment max over t ----
    float* red = reinterpret_cast<float*>(smem);        // [128][RED_STR]
    const int r0b = wm * 32 + (lane >> 2);
    const int c0b = wn * 64 + (lane & 3) * 2;
#pragma unroll
    for (int i = 0; i < 2; i++) {
#pragma unroll
        for (int q = 0; q < 8; q++) {
            const int r0 = r0b + i * 16;
            const int c0 = c0b + q * 8;
            red[r0 * RED_STR + c0]           = tanhf(acc[i][q][0] + biasS[c0]);
            red[r0 * RED_STR + c0 + 1]       = tanhf(acc[i][q][1] + biasS[c0 + 1]);
            red[(r0 + 8) * RED_STR + c0]     = tanhf(acc[i][q][2] + biasS[c0]);
            red[(r0 + 8) * RED_STR + c0 + 1] = tanhf(acc[i][q][3] + biasS[c0 + 1]);
        }
    }
    __syncthreads();

    const int p1 = entity_pos[2 * n];
    const int p2 = entity_pos[2 * n + 1];
    float* part = red + 128 * RED_STR;                   // [2][3][128]
    {
        const int half = tid >> 7, c = tid & 127;
        const int t0 = half ? 64 : 0;
        const int t1 = half ? (LP_ - 1) : 63;
        float m0 = NEG_, m1 = NEG_, m2 = NEG_;
        for (int t = t0; t <= t1; t++) {
            float v = red[t * RED_STR + c];
            if (t <= p1) m0 = fmaxf(m0, v);
            if (t >= p1 && t <= p2) m1 = fmaxf(m1, v);
            if (t >= p2) m2 = fmaxf(m2, v);
        }
        part[(half * 3 + 0) * 128 + c] = m0;
        part[(half * 3 + 1) * 128 + c] = m1;
        part[(half * 3 + 2) * 128 + c] = m2;
    }
    __syncthreads();

    if (tid < 128) {
        const size_t fo = (size_t)n * F3 + (size_t)(nb * 128 + tid) * 3;
#pragma unroll
        for (int s = 0; s < 3; s++)
            g_feat[fo + s] = fmaxf(part[s * 128 + tid], part[(3 + s) * 128 + tid]);
    }
}

// ---------------------------------------------------------------------------
// Kernel 3: out[n][c] = feat[n] @ out_w + out_b.
// 8 sentences per CTA: out_w (325KB) re-read from L2 only N/8=128 times
// (was 1024x = 333MB = the 47us). Smem feat reads are warp-broadcast.
// ---------------------------------------------------------------------------
#define SPC 8
__global__ __launch_bounds__(256) void out_gemm_kernel(
    const float* __restrict__ out_w, const float* __restrict__ out_b,
    float* __restrict__ out)
{
    __shared__ float sf[SPC * F3];                 // 48KB
    __shared__ float part[4][SPC][64];             // 8KB
    const int n0 = blockIdx.x * SPC;

    {
        const float4* src = reinterpret_cast<const float4*>(g_feat + (size_t)n0 * F3);
        float4* dst = reinterpret_cast<float4*>(sf);
        for (int i = threadIdx.x; i < SPC * F3 / 4; i += 256)
            dst[i] = src[i];
    }
    __syncthreads();

    const int g = threadIdx.x >> 6;                // j-group 0..3 (384 j each)
    const int c = threadIdx.x & 63;
    float a0 = 0.f, a1 = 0.f, a2 = 0.f, a3 = 0.f;
    float a4 = 0.f, a5 = 0.f, a6 = 0.f, a7 = 0.f;
    const int j0 = g * (F3 / 4);
    if (c < C_) {
#pragma unroll 2
        for (int j = j0; j < j0 + F3 / 4; j++) {
            const float w = out_w[j * C_ + c];     // coalesced, L2-resident
            a0 += sf[0 * F3 + j] * w;              // smem broadcast reads
            a1 += sf[1 * F3 + j] * w;
            a2 += sf[2 * F3 + j] * w;
            a3 += sf[3 * F3 + j] * w;
            a4 += sf[4 * F3 + j] * w;
            a5 += sf[5 * F3 + j] * w;
            a6 += sf[6 * F3 + j] * w;
            a7 += sf[7 * F3 + j] * w;
        }
    }
    part[g][0][c] = a0; part[g][1][c] = a1;
    part[g][2][c] = a2; part[g][3][c] = a3;
    part[g][4][c] = a4; part[g][5][c] = a5;
    part[g][6][c] = a6; part[g][7][c] = a7;
    __syncthreads();

#pragma unroll
    for (int pass = 0; pass < 2; pass++) {
        const int s = (threadIdx.x >> 6) + pass * 4;
        const int cc = threadIdx.x & 63;
        if (cc < C_) {
            float v = part[0][s][cc] + part[1][s][cc] +
                      part[2][s][cc] + part[3][s][cc] + out_b[cc];
            out[(size_t)(n0 + s) * C_ + cc] = v;
        }
    }
}

// ---------------------------------------------------------------------------
// Launch. Inputs: tokens, pf1, pf2, entity_pos, wordvec, pf1_emb, pf2_emb,
// conv_w, conv_b, out_w, out_b.  Output: float32 [N, C].
// ---------------------------------------------------------------------------
extern "C" void kernel_launch(void* const* d_in, const int* in_sizes, int n_in,
                              void* d_out, int out_size)
{
    const int*   tokens     = (const int*)d_in[0];
    const int*   pf1        = (const int*)d_in[1];
    const int*   pf2        = (const int*)d_in[2];
    const int*   entity_pos = (const int*)d_in[3];
    const float* wordvec    = (const float*)d_in[4];
    const float* pf1_emb    = (const float*)d_in[5];
    const float* pf2_emb    = (const float*)d_in[6];
    const float* conv_w     = (const float*)d_in[7];
    const float* conv_b     = (const float*)d_in[8];
    const float* out_w      = (const float*)d_in[9];
    const float* out_b      = (const float*)d_in[10];
    float* out = (float*)d_out;

    cudaFuncSetAttribute(conv_hmma_kernel,
                         cudaFuncAttributeMaxDynamicSharedMemorySize, SM_DYN);

    gather_kernel<<<N_ * L_, 128>>>(tokens, pf1, pf2, wordvec, pf1_emb, pf2_emb);
    wconv_kernel<<<(NF_ * KPAD) / 256, 256>>>(conv_w);
    conv_hmma_kernel<<<dim3(4, N_), 256, SM_DYN>>>(conv_b, entity_pos);
    out_gemm_kernel<<<N_ / SPC, 256>>>(out_w, out_b, out);
}

// round 17
// speedup vs baseline: 1.1313x; 1.0397x over previous
#include <cuda_runtime.h>
#include <cuda_fp16.h>
#include <cstdint>
#include <math.h>

// Problem constants
#define N_    1024
#define L_    128
#define WD_   300
#define PD_   50
#define D_    400          // WD + 2*PD
#define FS_   3
#define NF_   512
#define C_    53
#define LP_   126          // L - FS + 1
#define KTOT  1200         // FS * D
#define KPAD  1216         // padded to 19*64
#define KC    64
#define NKC   19
#define NEG_  (-1e30f)
#define F3    (3 * NF_)

// ---------------------------------------------------------------------------
// Scratch (device globals; no allocs allowed)
// ---------------------------------------------------------------------------
__device__ __align__(256) __half g_X[(size_t)N_ * L_ * D_ + 2048];   // fp16 X
__device__ __align__(256) __half g_W[NF_ * KPAD];                    // fp16 W
__device__ float g_feat[(size_t)N_ * F3];        // [n][f*3+seg]

// ---------------------------------------------------------------------------
// Helpers (baseline ISA only: cp.async / ldmatrix / mma.sync)
// ---------------------------------------------------------------------------
__device__ __forceinline__ uint32_t smem_u32(const void* p) {
    uint32_t a;
    asm("{ .reg .u64 t; cvta.to.shared.u64 t, %1; cvt.u32.u64 %0, t; }" : "=r"(a) : "l"(p));
    return a;
}
#define CP_ASYNC16(dst, src) \
    asm volatile("cp.async.cg.shared.global [%0], [%1], 16;" :: "r"(dst), "l"(src) : "memory")
#define CP_COMMIT()  asm volatile("cp.async.commit_group;" ::: "memory")
#define CP_WAIT1()   asm volatile("cp.async.wait_group 1;" ::: "memory")
#define CP_WAIT0()   asm volatile("cp.async.wait_group 0;" ::: "memory")

#define LDSM_X4(d0, d1, d2, d3, addr) \
    asm volatile("ldmatrix.sync.aligned.m8n8.x4.shared.b16 {%0,%1,%2,%3}, [%4];" \
                 : "=r"(d0), "=r"(d1), "=r"(d2), "=r"(d3) : "r"(addr))

#define MMAF16(cc, a0, a1, a2, a3, b0, b1) \
    asm volatile("mma.sync.aligned.m16n8k16.row.col.f32.f16.f16.f32 " \
                 "{%0,%1,%2,%3}, {%4,%5,%6,%7}, {%8,%9}, {%0,%1,%2,%3};" \
                 : "+f"((cc)[0]), "+f"((cc)[1]), "+f"((cc)[2]), "+f"((cc)[3]) \
                 : "r"(a0), "r"(a1), "r"(a2), "r"(a3), "r"(b0), "r"(b1))

// ---------------------------------------------------------------------------
// Kernel 1: embedding gather -> fp16 (R11-proven, untouched)
// ---------------------------------------------------------------------------
__global__ __launch_bounds__(128) void gather_kernel(
    const int* __restrict__ tokens, const int* __restrict__ pf1,
    const int* __restrict__ pf2,
    const float* __restrict__ wordvec, const float* __restrict__ pf1_emb,
    const float* __restrict__ pf2_emb)
{
    int id = blockIdx.x;                     // (n,l)
    size_t base = (size_t)id * D_;
    int t = threadIdx.x;
    if (t < 75) {
        float4 v = reinterpret_cast<const float4*>(wordvec + (size_t)tokens[id] * WD_)[t];
        __half h[4] = {__float2half(v.x), __float2half(v.y),
                       __float2half(v.z), __float2half(v.w)};
        *reinterpret_cast<uint2*>(&g_X[base + t * 4]) = *reinterpret_cast<uint2*>(h);
    } else if (t < 100) {
        int j = t - 75;
        float2 v = reinterpret_cast<const float2*>(pf1_emb + pf1[id] * PD_)[j];
        __half h[2] = {__float2half(v.x), __float2half(v.y)};
        *reinterpret_cast<uint32_t*>(&g_X[base + WD_ + j * 2]) = *reinterpret_cast<uint32_t*>(h);
    } else if (t < 125) {
        int j = t - 100;
        float2 v = reinterpret_cast<const float2*>(pf2_emb + pf2[id] * PD_)[j];
        __half h[2] = {__float2half(v.x), __float2half(v.y)};
        *reinterpret_cast<uint32_t*>(&g_X[base + WD_ + PD_ + j * 2]) = *reinterpret_cast<uint32_t*>(h);
    }
}

// ---------------------------------------------------------------------------
// Kernel 1b: convert conv_w to fp16, zero-padded K 1200->1216
// ---------------------------------------------------------------------------
__global__ __launch_bounds__(256) void wconv_kernel(const float* __restrict__ conv_w)
{
    int idx = blockIdx.x * 256 + threadIdx.x;      // 0 .. NF_*KPAD-1
    int f = idx / KPAD, k = idx % KPAD;
    float v = (k < KTOT) ? conv_w[(size_t)f * KTOT + k] : 0.f;
    g_W[idx] = __float2half(v);
}

// ---------------------------------------------------------------------------
// Kernel 2: fp16 mma.sync conv GEMM + tanh + pool.
// R11 config (proven): grid (4, N_), 8 warps = 4(M) x 2(N), warp tile 32x64,
// 2 CTAs/SM.  ONE structural change vs R11: 3-stage cp.async ring with a
// SINGLE __syncthreads per kc (reuse distance 3 makes the top-of-loop sync
// sufficient to protect the overwrite target).
// ---------------------------------------------------------------------------
#define STAGE_SZ 32768
#define B_OFF    16384
#define SM_BIAS  98304                 // after the 3 stages
#define SM_DYN   99328
#define RED_STR  132

struct LoadCtx { size_t xbase; int nb; };

__device__ __forceinline__ void load_stage(uint32_t sbase, int tid,
                                           const LoadCtx& lc, int k0)
{
#pragma unroll
    for (int i = 0; i < 4; i++) {          // A: 128 rows x 8 chunks of 16B
        int idx = tid + i * 256;
        int r = idx >> 3, c = idx & 7;
        uint32_t d = sbase + r * 128 + ((uint32_t)(c ^ (r & 7)) << 4);
        CP_ASYNC16(d, g_X + lc.xbase + (size_t)r * D_ + k0 + c * 8);
    }
#pragma unroll
    for (int i = 0; i < 4; i++) {          // B: 128 rows x 8 chunks of 16B
        int idx = tid + i * 256;
        int r = idx >> 3, c = idx & 7;
        uint32_t d = sbase + B_OFF + r * 128 + ((uint32_t)(c ^ (r & 7)) << 4);
        CP_ASYNC16(d, g_W + (size_t)(lc.nb * 128 + r) * KPAD + k0 + c * 8);
    }
}

__global__ __launch_bounds__(256, 2) void conv_hmma_kernel(
    const float* __restrict__ conv_b, const int* __restrict__ entity_pos)
{
    extern __shared__ char smem[];
    const uint32_t sb = smem_u32(smem);
    const int tid  = threadIdx.x;
    const int lane = tid & 31, wid = tid >> 5;
    const int wm = wid & 3, wn = wid >> 2;       // warp grid 4(M) x 2(N)
    const int nb = blockIdx.x;                    // filter quarter
    const int n  = blockIdx.y;                    // sentence

    float* biasS = reinterpret_cast<float*>(smem + SM_BIAS);
    if (tid < 128) biasS[tid] = conv_b[nb * 128 + tid];

    LoadCtx lc;
    lc.xbase = (size_t)n * (L_ * D_);
    lc.nb = nb;

    const int rowA = wm * 32 + ((lane >> 3) & 1) * 8 + (lane & 7);
    const int haA  = lane >> 4;
    const uint32_t offA = rowA * 128;
    const int saA = rowA & 7;
    const int rowB = wn * 64 + ((lane >> 4) & 1) * 8 + (lane & 7);
    const int hbB  = (lane >> 3) & 1;
    const uint32_t offB = rowB * 128;
    const int sbB = rowB & 7;

    float acc[2][8][4];
#pragma unroll
    for (int i = 0; i < 2; i++)
#pragma unroll
        for (int q = 0; q < 8; q++)
#pragma unroll
            for (int v = 0; v < 4; v++) acc[i][q][v] = 0.f;

    // 3-stage ring prologue: stages 0,1 in flight
    load_stage(sb, tid, lc, 0);
    CP_COMMIT();
    load_stage(sb + STAGE_SZ, tid, lc, KC);
    CP_COMMIT();

    uint32_t stgC = sb;                       // compute stage (kc%3)
    uint32_t stgL = sb + 2 * STAGE_SZ;        // next load target ((kc+2)%3)

    for (int kc = 0; kc < NKC; kc++) {
        if (kc + 1 < NKC) CP_WAIT1(); else CP_WAIT0();   // stage kc resident
        __syncthreads();   // all warps finished iter kc-1 (stage (kc+2)%3)

        if (kc + 2 < NKC) {
            load_stage(stgL, tid, lc, (kc + 2) * KC);
            CP_COMMIT();
            stgL += STAGE_SZ;
            if (stgL == sb + 3 * STAGE_SZ) stgL = sb;
        }

        const uint32_t stg = stgC;
#pragma unroll
        for (int ks = 0; ks < 4; ks++) {
            uint32_t a[2][4], b[4][4];
#pragma unroll
            for (int i = 0; i < 2; i++) {
                uint32_t ad = stg + offA + i * 2048
                            + ((uint32_t)((ks * 2 + haA) ^ saA) << 4);
                LDSM_X4(a[i][0], a[i][1], a[i][2], a[i][3], ad);
            }
#pragma unroll
            for (int j = 0; j < 4; j++) {
                uint32_t bd = stg + B_OFF + offB + j * 2048
                            + ((uint32_t)((ks * 2 + hbB) ^ sbB) << 4);
                LDSM_X4(b[j][0], b[j][1], b[j][2], b[j][3], bd);
            }
#pragma unroll
            for (int j = 0; j < 4; j++) {
#pragma unroll
                for (int i = 0; i < 2; i++) {
                    MMAF16(acc[i][j * 2],     a[i][0], a[i][1], a[i][2], a[i][3],
                           b[j][0], b[j][1]);
                    MMAF16(acc[i][j * 2 + 1], a[i][0], a[i][1], a[i][2], a[i][3],
                           b[j][2], b[j][3]);
                }
            }
        }
        stgC += STAGE_SZ;
        if (stgC == sb + 3 * STAGE_SZ) stgC = sb;
    }
    __syncthreads();   // drain all stage reads before red overwrites smem

    // ---- epilogue: bias + tanh -> smem, then 3-segment max over t ----
    float* red = reinterpret_cast<float*>(smem);        // [128][RED_STR]
    const int r0b = wm * 32 + (lane >> 2);
    const int c0b = wn * 64 + (lane & 3) * 2;
#pragma unroll
    for (int i = 0; i < 2; i++) {
#pragma unroll
        for (int q = 0; q < 8; q++) {
            const int r0 = r0b + i * 16;
            const int c0 = c0b + q * 8;
            red[r0 * RED_STR + c0]           = tanhf(acc[i][q][0] + biasS[c0]);
            red[r0 * RED_STR + c0 + 1]       = tanhf(acc[i][q][1] + biasS[c0 + 1]);
            red[(r0 + 8) * RED_STR + c0]     = tanhf(acc[i][q][2] + biasS[c0]);
            red[(r0 + 8) * RED_STR + c0 + 1] = tanhf(acc[i][q][3] + biasS[c0 + 1]);
        }
    }
    __syncthreads();

    const int p1 = entity_pos[2 * n];
    const int p2 = entity_pos[2 * n + 1];
    float* part = red + 128 * RED_STR;                   // [2][3][128]
    {
        const int half = tid >> 7, c = tid & 127;
        const int t0 = half ? 64 : 0;
        const int t1 = half ? (LP_ - 1) : 63;
        float m0 = NEG_, m1 = NEG_, m2 = NEG_;
        for (int t = t0; t <= t1; t++) {
            float v = red[t * RED_STR + c];
            if (t <= p1) m0 = fmaxf(m0, v);
            if (t >= p1 && t <= p2) m1 = fmaxf(m1, v);
            if (t >= p2) m2 = fmaxf(m2, v);
        }
        part[(half * 3 + 0) * 128 + c] = m0;
        part[(half * 3 + 1) * 128 + c] = m1;
        part[(half * 3 + 2) * 128 + c] = m2;
    }
    __syncthreads();

    if (tid < 128) {
        const size_t fo = (size_t)n * F3 + (size_t)(nb * 128 + tid) * 3;
#pragma unroll
        for (int s = 0; s < 3; s++)
            g_feat[fo + s] = fmaxf(part[s * 128 + tid], part[(3 + s) * 128 + tid]);
    }
}

// ---------------------------------------------------------------------------
// Kernel 3: out[n][c] = feat[n] @ out_w + out_b  (R11-proven, reverted)
// ---------------------------------------------------------------------------
__global__ __launch_bounds__(256) void out_gemm_kernel(
    const float* __restrict__ out_w, const float* __restrict__ out_b,
    float* __restrict__ out)
{
    __shared__ float sf[F3];
    __shared__ float part[4][64];
    const int n = blockIdx.x;

    for (int i = threadIdx.x; i < F3; i += 256)
        sf[i] = g_feat[(size_t)n * F3 + i];
    __syncthreads();

    const int g = threadIdx.x >> 6;
    const int c = threadIdx.x & 63;
    float a = 0.f;
    if (c < C_) {
        const int j0 = g * (F3 / 4);
#pragma unroll 4
        for (int j = j0; j < j0 + (F3 / 4); j++)
            a += sf[j] * out_w[j * C_ + c];
    }
    part[g][c] = a;
    __syncthreads();

    if (threadIdx.x < C_) {
        float s = part[0][threadIdx.x] + part[1][threadIdx.x] +
                  part[2][threadIdx.x] + part[3][threadIdx.x] + out_b[threadIdx.x];
        out[(size_t)n * C_ + threadIdx.x] = s;
    }
}

// ---------------------------------------------------------------------------
// Launch. Inputs: tokens, pf1, pf2, entity_pos, wordvec, pf1_emb, pf2_emb,
// conv_w, conv_b, out_w, out_b.  Output: float32 [N, C].
// ---------------------------------------------------------------------------
extern "C" void kernel_launch(void* const* d_in, const int* in_sizes, int n_in,
                              void* d_out, int out_size)
{
    const int*   tokens     = (const int*)d_in[0];
    const int*   pf1        = (const int*)d_in[1];
    const int*   pf2        = (const int*)d_in[2];
    const int*   entity_pos = (const int*)d_in[3];
    const float* wordvec    = (const float*)d_in[4];
    const float* pf1_emb    = (const float*)d_in[5];
    const float* pf2_emb    = (const float*)d_in[6];
    const float* conv_w     = (const float*)d_in[7];
    const float* conv_b     = (const float*)d_in[8];
    const float* out_w      = (const float*)d_in[9];
    const float* out_b      = (const float*)d_in[10];
    float* out = (float*)d_out;

    cudaFuncSetAttribute(conv_hmma_kernel,
                         cudaFuncAttributeMaxDynamicSharedMemorySize, SM_DYN);

    gather_kernel<<<N_ * L_, 128>>>(tokens, pf1, pf2, wordvec, pf1_emb, pf2_emb);
    wconv_kernel<<<(NF_ * KPAD) / 256, 256>>>(conv_w);
    conv_hmma_kernel<<<dim3(4, N_), 256, SM_DYN>>>(conv_b, entity_pos);
    out_gemm_kernel<<<N_, 256>>>(out_w, out_b, out);
}